// round 1
// baseline (speedup 1.0000x reference)
#include <cuda_runtime.h>
#include <math.h>

// Problem constants
#define BB   8
#define SS   2048
#define HH   16
#define DHH  64
#define DD   1024            // H*DH
#define MM   (BB*SS)         // 16384

// ---------------- scratch (__device__ globals; allocation-free) -------------
__device__ float g_Q     [BB*SS*DD];   // Q = Q_seq @ WQ        (B,S,D)
__device__ float g_K     [BB*SS*DD];   // K = K_seq @ WK        (B,S,D)
__device__ float g_QK    [BB*SS*DD];   // QK in (B,H,S,DH) contiguous
__device__ float g_logits[BB*HH*SS];   // (B,H,S)
__device__ float g_gq    [BB*HH*DHH];  // (B,H,DH) flattened = (B, D)
__device__ float g_gk    [BB*HH*DHH];

// ---------------------------------------------------------------------------
// SGEMM: C[M=16384, N=1024] = A[M,K=1024] @ B[K,N]
// BM=128 BN=128 BK=8, 256 threads, 8x8 per thread.
// SCALED_RES variant: A_eff[m,k] = A[m,k] * gscale[b*D + k]  (b = m/S),
//                     C[m,n] = A_eff@B + res[m,n]
// ---------------------------------------------------------------------------
template<bool SCALED_RES>
__global__ __launch_bounds__(256) void sgemm_kernel(
    const float* __restrict__ A, const float* __restrict__ Bm,
    float* __restrict__ C, const float* __restrict__ gscale,
    const float* __restrict__ res)
{
    const int N = DD, K = DD;
    __shared__ __align__(16) float As[8][128];
    __shared__ __align__(16) float Bs[8][128];

    const int tid = threadIdx.x;
    const int colBase = blockIdx.x * 128;
    const int rowBase = blockIdx.y * 128;

    const int arow = tid >> 1, ac4 = (tid & 1) * 4;   // A tile: 128 x 8
    const int brow = tid >> 5, bc4 = (tid & 31) * 4;  // B tile: 8 x 128
    const int ty = tid >> 4, tx = tid & 15;
    const int rf = ty * 8, cf = tx * 8;

    float acc[8][8];
    #pragma unroll
    for (int i = 0; i < 8; i++)
        #pragma unroll
        for (int j = 0; j < 8; j++) acc[i][j] = 0.f;

    const float* grow = nullptr;
    if (SCALED_RES) grow = gscale + (size_t)(rowBase >> 11) * DD;  // b = rowBase/2048

    const float* aptr = A + (size_t)(rowBase + arow) * K + ac4;
    const float* bptr = Bm + (size_t)brow * N + colBase + bc4;

    for (int k0 = 0; k0 < K; k0 += 8) {
        float4 av = *(const float4*)(aptr + k0);
        if (SCALED_RES) {
            av.x *= grow[k0 + ac4 + 0];
            av.y *= grow[k0 + ac4 + 1];
            av.z *= grow[k0 + ac4 + 2];
            av.w *= grow[k0 + ac4 + 3];
        }
        As[ac4 + 0][arow] = av.x;
        As[ac4 + 1][arow] = av.y;
        As[ac4 + 2][arow] = av.z;
        As[ac4 + 3][arow] = av.w;

        float4 bv = *(const float4*)(bptr + (size_t)k0 * N);
        *(float4*)&Bs[brow][bc4] = bv;

        __syncthreads();

        #pragma unroll
        for (int kk = 0; kk < 8; kk++) {
            float4 a0 = *(const float4*)&As[kk][rf];
            float4 a1 = *(const float4*)&As[kk][rf + 4];
            float4 b0 = *(const float4*)&Bs[kk][cf];
            float4 b1 = *(const float4*)&Bs[kk][cf + 4];
            float af[8] = {a0.x, a0.y, a0.z, a0.w, a1.x, a1.y, a1.z, a1.w};
            float bf[8] = {b0.x, b0.y, b0.z, b0.w, b1.x, b1.y, b1.z, b1.w};
            #pragma unroll
            for (int i = 0; i < 8; i++)
                #pragma unroll
                for (int j = 0; j < 8; j++)
                    acc[i][j] += af[i] * bf[j];
        }
        __syncthreads();
    }

    #pragma unroll
    for (int i = 0; i < 8; i++) {
        float* crow = C + (size_t)(rowBase + rf + i) * N + colBase + cf;
        if (SCALED_RES) {
            const float* rrow = res + (size_t)(rowBase + rf + i) * N + colBase + cf;
            #pragma unroll
            for (int j = 0; j < 8; j++) crow[j] = acc[i][j] + rrow[j];
        } else {
            #pragma unroll
            for (int j = 0; j < 8; j++) crow[j] = acc[i][j];
        }
    }
}

// ---------------------------------------------------------------------------
// logits[b,h,s] = scale * sum_d X[(b*S+s)*D + d] * W[d*H + h]
//                 - (1 - mask[b*S+s]) * 1e8
// One block per row m. 256 threads: h = tid>>4, g = tid&15.
// ---------------------------------------------------------------------------
__global__ __launch_bounds__(256) void logits_kernel(
    const float* __restrict__ X, const float* __restrict__ W,
    const float* __restrict__ mask, float* __restrict__ logits)
{
    const int m = blockIdx.x;
    const int b = m >> 11, s = m & (SS - 1);
    const int tid = threadIdx.x;
    const int h = tid >> 4, g = tid & 15;
    const float* xrow = X + (size_t)m * DD;

    float acc = 0.f;
    #pragma unroll 4
    for (int d = g; d < DD; d += 16)
        acc += xrow[d] * W[d * HH + h];

    __shared__ float red[256];
    red[tid] = acc;
    __syncthreads();
    if (tid < HH) {
        float v = 0.f;
        #pragma unroll
        for (int g2 = 0; g2 < 16; g2++) v += red[tid * 16 + g2];
        logits[((size_t)(b * HH + tid)) * SS + s] =
            v * 0.125f - (1.f - mask[m]) * 1e8f;
    }
}

// ---------------------------------------------------------------------------
// att = softmax(logits[b,h,:]);  gout[b,h,dh] = sum_s att[s]*src[b,h,s,dh]
// strides parameterize src layout ((B,S,D) head-sliced vs (B,H,S,DH)).
// One block per (b,h). 256 threads.
// ---------------------------------------------------------------------------
__global__ __launch_bounds__(256) void softmax_wsum_kernel(
    const float* __restrict__ logits, const float* __restrict__ src,
    float* __restrict__ gout, long strideB, long strideH, int strideS)
{
    const int b = blockIdx.x >> 4, h = blockIdx.x & 15;
    const int tid = threadIdx.x;
    const float* lrow = logits + (size_t)(b * HH + h) * SS;

    __shared__ float att[SS];   // 8 KB
    __shared__ float red[256];

    float mx = -3.4e38f;
    for (int s = tid; s < SS; s += 256) mx = fmaxf(mx, lrow[s]);
    red[tid] = mx; __syncthreads();
    for (int off = 128; off > 0; off >>= 1) {
        if (tid < off) red[tid] = fmaxf(red[tid], red[tid + off]);
        __syncthreads();
    }
    mx = red[0];
    __syncthreads();

    float sum = 0.f;
    for (int s = tid; s < SS; s += 256) {
        float e = expf(lrow[s] - mx);
        att[s] = e;
        sum += e;
    }
    red[tid] = sum; __syncthreads();
    for (int off = 128; off > 0; off >>= 1) {
        if (tid < off) red[tid] += red[tid + off];
        __syncthreads();
    }
    const float inv = 1.f / red[0];
    __syncthreads();

    const int dh = tid & 63, j = tid >> 6;     // 4 s-lanes x 64 dh
    const float* base = src + (size_t)b * strideB + (size_t)h * strideH + dh;
    float acc = 0.f;
    for (int s = j; s < SS; s += 4)
        acc += att[s] * base[(size_t)s * strideS];

    red[tid] = acc; __syncthreads();
    if (j == 0) {
        acc = red[dh] + red[64 + dh] + red[128 + dh] + red[192 + dh];
        gout[(b * HH + h) * DHH + dh] = acc * inv;
    }
}

// ---------------------------------------------------------------------------
// g_QK[b,h,s,dh] = g_K[(b*S+s)*D + h*64+dh] * g_gq[(b*H+h)*64+dh]
// ---------------------------------------------------------------------------
__global__ __launch_bounds__(256) void scale_qk_kernel()
{
    const int idx = blockIdx.x * 256 + threadIdx.x;   // 16,777,216 total
    const int b  = idx >> 21;
    const int h  = (idx >> 17) & 15;
    const int s  = (idx >> 6) & 2047;
    const int dh = idx & 63;
    g_QK[idx] = g_K[((size_t)(b * SS + s)) * DD + h * DHH + dh]
              * g_gq[(b * HH + h) * DHH + dh];
}

// ---------------------------------------------------------------------------
extern "C" void kernel_launch(void* const* d_in, const int* in_sizes, int n_in,
                              void* d_out, int out_size)
{
    const float* Qseq  = (const float*)d_in[0];
    const float* Kseq  = (const float*)d_in[1];
    const float* Qmask = (const float*)d_in[2];
    const float* Kmask = (const float*)d_in[3];
    const float* WQ    = (const float*)d_in[4];
    const float* WK    = (const float*)d_in[5];
    const float* Wq    = (const float*)d_in[6];
    const float* Wk    = (const float*)d_in[7];
    const float* WP    = (const float*)d_in[8];
    float* out = (float*)d_out;

    float *pQ, *pK, *pQK, *pL, *pgq, *pgk;
    cudaGetSymbolAddress((void**)&pQ,  g_Q);
    cudaGetSymbolAddress((void**)&pK,  g_K);
    cudaGetSymbolAddress((void**)&pQK, g_QK);
    cudaGetSymbolAddress((void**)&pL,  g_logits);
    cudaGetSymbolAddress((void**)&pgq, g_gq);
    cudaGetSymbolAddress((void**)&pgk, g_gk);

    dim3 gg(DD / 128, MM / 128);

    // 1) Q = Q_seq @ WQ ; 2) K = K_seq @ WK
    sgemm_kernel<false><<<gg, 256>>>(Qseq, WQ, pQ, nullptr, nullptr);
    sgemm_kernel<false><<<gg, 256>>>(Kseq, WK, pK, nullptr, nullptr);

    // 3) q logits + softmax + global_q
    logits_kernel<<<MM, 256>>>(pQ, Wq, Qmask, pL);
    softmax_wsum_kernel<<<BB * HH, 256>>>(pL, pQ, pgq,
                                          (long)SS * DD, (long)DHH, DD);

    // 4) QK = Kh * global_q   (stored (B,H,S,DH) contiguous)
    scale_qk_kernel<<<(BB * SS * DD) / 256, 256>>>();

    // 5) k logits (head-mixing reshape == same linear row layout) + softmax + global_k
    logits_kernel<<<MM, 256>>>(pQK, Wk, Kmask, pL);
    softmax_wsum_kernel<<<BB * HH, 256>>>(pL, pQK, pgk,
                                          (long)HH * SS * DHH, (long)SS * DHH, DHH);

    // 6) out = ((gk ⊙ Q) @ WP) + Q
    sgemm_kernel<true><<<gg, 256>>>(pQ, WP, out, pgk, pQ);
}

// round 3
// speedup vs baseline: 1.8294x; 1.8294x over previous
#include <cuda_runtime.h>
#include <cuda_bf16.h>
#include <math.h>
#include <stdint.h>

// Problem constants
#define BB   8
#define SS   2048
#define HH   16
#define DHH  64
#define DD   1024            // H*DH
#define MM   (BB*SS)         // 16384

// ---------------- scratch (__device__ globals; allocation-free) -------------
__device__ float g_Q     [BB*SS*DD];   // Q = Q_seq @ WQ        (B,S,D)
__device__ float g_K     [BB*SS*DD];   // K = K_seq @ WK        (B,S,D)
__device__ float g_QK    [BB*SS*DD];   // QK in (B,H,S,DH) contiguous
__device__ float g_logits[BB*HH*SS];   // (B,H,S)
__device__ float g_gq    [BB*HH*DHH];  // (B,H,DH) = (B, D)
__device__ float g_gk    [BB*HH*DHH];
__device__ __nv_bfloat16 g_Bhi[DD*DD]; // split+transposed weight Bt[n,k]
__device__ __nv_bfloat16 g_Blo[DD*DD];

// ======================= PTX helpers ========================================
__device__ __forceinline__ uint32_t smem_to_u32(const void* p) {
    uint32_t a;
    asm("{ .reg .u64 t; cvta.to.shared.u64 t, %1; cvt.u32.u64 %0, t; }"
        : "=r"(a) : "l"(p));
    return a;
}
#define LDSM4(r, addr) asm volatile( \
    "ldmatrix.sync.aligned.m8n8.x4.shared.b16 {%0,%1,%2,%3}, [%4];" \
    : "=r"((r)[0]), "=r"((r)[1]), "=r"((r)[2]), "=r"((r)[3]) : "r"(addr))
#define MMA_BF16(d, a, b) asm volatile( \
    "mma.sync.aligned.m16n8k16.row.col.f32.bf16.bf16.f32 " \
    "{%0,%1,%2,%3}, {%4,%5,%6,%7}, {%8,%9}, {%0,%1,%2,%3};" \
    : "+f"((d)[0]), "+f"((d)[1]), "+f"((d)[2]), "+f"((d)[3]) \
    : "r"((a)[0]), "r"((a)[1]), "r"((a)[2]), "r"((a)[3]), \
      "r"((b)[0]), "r"((b)[1]))
__device__ __forceinline__ void cp16(uint32_t dst, const void* src) {
    asm volatile("cp.async.cg.shared.global [%0], [%1], 16;"
                 :: "r"(dst), "l"(src) : "memory");
}
#define CP_COMMIT()  asm volatile("cp.async.commit_group;" ::: "memory")
#define CP_WAIT_1()  asm volatile("cp.async.wait_group 1;" ::: "memory")
#define CP_WAIT_0()  asm volatile("cp.async.wait_group 0;" ::: "memory")

__device__ __forceinline__ uint32_t pack_hi(float a, float b) {
    __nv_bfloat162 t;
    t.x = __float2bfloat16(a);
    t.y = __float2bfloat16(b);
    return *(uint32_t*)&t;
}
__device__ __forceinline__ uint32_t pack_lo(float a, float b) {
    float ra = a - __bfloat162float(__float2bfloat16(a));
    float rb = b - __bfloat162float(__float2bfloat16(b));
    __nv_bfloat162 t;
    t.x = __float2bfloat16(ra);
    t.y = __float2bfloat16(rb);
    return *(uint32_t*)&t;
}

// ======================= HMMA split-bf16 GEMM ===============================
// C[M,N=1024] = A_f32 @ Bt_bf16(hi/lo) (+res), A optionally scaled per (b,k).
// CTA tile 128m x 64n, BK=32, 8 warps (warp tile 32x32), double buffered.
// SMEM stage layout (80B padded rows => conflict-free ldmatrix):
//   A_hi: [128][80B] @ 0        (10240 B)
//   A_lo: [128][80B] @ 10240
//   B_hi: [ 64][80B] @ 20480    ( 5120 B)
//   B_lo: [ 64][80B] @ 25600
#define STAGE_B   30720
#define GEMM_SMEM (2 * STAGE_B)
#define KB        32          // 1024 / 32

template<bool SC, bool RES>
__global__ __launch_bounds__(256, 2) void hmma_gemm_kernel(
    const float* __restrict__ A,
    const __nv_bfloat16* __restrict__ Bhi, const __nv_bfloat16* __restrict__ Blo,
    float* __restrict__ C, const float* __restrict__ g,
    const float* __restrict__ res)
{
    extern __shared__ __align__(128) char smem[];
    const uint32_t sb = smem_to_u32(smem);
    const int tid = threadIdx.x;
    const int lane = tid & 31;
    const int wid  = tid >> 5;
    const int warpM = wid >> 1;            // 0..3
    const int warpN = wid & 1;             // 0..1
    const int colBase = blockIdx.x * 64;
    const int rowBase = blockIdx.y * 128;

    // ---- A load mapping: 4 x 16B fp32 chunks per thread per k-block
    const int am = tid >> 3;               // 0..31 (+32*i)
    const int ac = (tid & 7) * 4;          // k offset (floats)
    const float* aPtr[4];
    uint32_t aSts[4];
    #pragma unroll
    for (int i = 0; i < 4; i++) {
        const int m = am + 32 * i;
        aPtr[i] = A + (size_t)(rowBase + m) * DD + ac;
        aSts[i] = sb + m * 80 + ac * 2;    // byte offset inside A region
    }
    const float* grow = SC ? (g + (size_t)(blockIdx.y >> 4) * DD + ac) : (const float*)0;

    // ---- B cp.async mapping: 2 chunks (hi,lo) per thread per k-block
    const int bn = tid >> 2;               // 0..63
    const int bc = tid & 3;                // 16B chunk in 64B row
    const size_t bSrcOff = ((size_t)(colBase + bn) * DD + bc * 8);
    const uint32_t bDst = bn * 80 + bc * 16;

    // ---- prologue: kb = 0
    float4 rA[4];
    float4 gs;
    #pragma unroll
    for (int i = 0; i < 4; i++) rA[i] = *(const float4*)(aPtr[i]);
    if (SC) gs = *(const float4*)(grow);
    cp16(sb + 20480 + bDst, Bhi + bSrcOff);
    cp16(sb + 25600 + bDst, Blo + bSrcOff);
    CP_COMMIT();

    float acc[2][4][4];
    #pragma unroll
    for (int mf = 0; mf < 2; mf++)
        #pragma unroll
        for (int nf = 0; nf < 4; nf++)
            #pragma unroll
            for (int q = 0; q < 4; q++) acc[mf][nf][q] = 0.f;

    // ldmatrix addresses (lane-dependent part)
    const int lrow = lane & 15;
    const int lc16 = (lane >> 4) * 16;

    for (int kb = 0; kb < KB; kb++) {
        const uint32_t st = sb + (kb & 1) * STAGE_B;

        // store A (convert fp32 -> hi/lo bf16), values are for this kb
        #pragma unroll
        for (int i = 0; i < 4; i++) {
            float4 v = rA[i];
            if (SC) { v.x *= gs.x; v.y *= gs.y; v.z *= gs.z; v.w *= gs.w; }
            uint2 h = make_uint2(pack_hi(v.x, v.y), pack_hi(v.z, v.w));
            uint2 l = make_uint2(pack_lo(v.x, v.y), pack_lo(v.z, v.w));
            *(uint2*)(smem + (kb & 1) * STAGE_B + (aSts[i] - sb))        = h;
            *(uint2*)(smem + (kb & 1) * STAGE_B + (aSts[i] - sb) + 10240) = l;
        }

        if (kb + 1 < KB) {
            const int ko = (kb + 1) * 32;
            #pragma unroll
            for (int i = 0; i < 4; i++) rA[i] = *(const float4*)(aPtr[i] + ko);
            if (SC) gs = *(const float4*)(grow + ko);
            const uint32_t st2 = sb + ((kb + 1) & 1) * STAGE_B;
            cp16(st2 + 20480 + bDst, Bhi + bSrcOff + (size_t)ko);
            cp16(st2 + 25600 + bDst, Blo + bSrcOff + (size_t)ko);
            CP_COMMIT();
            CP_WAIT_1();
        } else {
            CP_WAIT_0();
        }
        __syncthreads();

        // ---- compute on stage st
        const uint32_t aBase = st + (warpM * 32 + lrow) * 80 + lc16;
        const uint32_t bBase = st + 20480 + (warpN * 32 + lrow) * 80 + lc16;
        #pragma unroll
        for (int ks = 0; ks < 2; ks++) {
            uint32_t af[2][2][4];   // [ver][mf]
            uint32_t bf[2][4][2];   // [ver][nf]
            #pragma unroll
            for (int ver = 0; ver < 2; ver++) {
                #pragma unroll
                for (int mf = 0; mf < 2; mf++)
                    LDSM4(af[ver][mf], aBase + ver * 10240 + mf * 16 * 80 + ks * 32);
                #pragma unroll
                for (int np = 0; np < 2; np++) {
                    uint32_t r[4];
                    LDSM4(r, bBase + ver * 5120 + np * 16 * 80 + ks * 32);
                    bf[ver][np * 2 + 0][0] = r[0]; bf[ver][np * 2 + 0][1] = r[2];
                    bf[ver][np * 2 + 1][0] = r[1]; bf[ver][np * 2 + 1][1] = r[3];
                }
            }
            #pragma unroll
            for (int mf = 0; mf < 2; mf++)
                #pragma unroll
                for (int nf = 0; nf < 4; nf++) {
                    MMA_BF16(acc[mf][nf], af[0][mf], bf[0][nf]);
                    MMA_BF16(acc[mf][nf], af[0][mf], bf[1][nf]);
                    MMA_BF16(acc[mf][nf], af[1][mf], bf[0][nf]);
                }
        }
        __syncthreads();
    }

    // ---- epilogue
    const int er = lane >> 2;
    const int ec = (lane & 3) * 2;
    #pragma unroll
    for (int mf = 0; mf < 2; mf++) {
        const int row0 = rowBase + warpM * 32 + mf * 16 + er;
        #pragma unroll
        for (int nf = 0; nf < 4; nf++) {
            const int col = colBase + warpN * 32 + nf * 8 + ec;
            float2 v0 = make_float2(acc[mf][nf][0], acc[mf][nf][1]);
            float2 v1 = make_float2(acc[mf][nf][2], acc[mf][nf][3]);
            if (RES) {
                const float2 r0 = *(const float2*)(res + (size_t)row0 * DD + col);
                const float2 r1 = *(const float2*)(res + (size_t)(row0 + 8) * DD + col);
                v0.x += r0.x; v0.y += r0.y; v1.x += r1.x; v1.y += r1.y;
            }
            *(float2*)(C + (size_t)row0 * DD + col) = v0;
            *(float2*)(C + (size_t)(row0 + 8) * DD + col) = v1;
        }
    }
}

// ======================= weight transpose + split ===========================
__global__ __launch_bounds__(256) void wsplit_kernel(
    const float* __restrict__ W, __nv_bfloat16* __restrict__ bhi,
    __nv_bfloat16* __restrict__ blo)
{
    __shared__ float tile[32][33];
    const int tx = threadIdx.x & 31, ty0 = threadIdx.x >> 5;
    const int nbase = blockIdx.x * 32, kbase = blockIdx.y * 32;
    #pragma unroll
    for (int j = 0; j < 4; j++) {
        int r = ty0 + j * 8;
        tile[r][tx] = W[(size_t)(kbase + r) * DD + nbase + tx];
    }
    __syncthreads();
    #pragma unroll
    for (int j = 0; j < 4; j++) {
        int n = nbase + ty0 + j * 8;
        int k = kbase + tx;
        float v = tile[tx][ty0 + j * 8];
        __nv_bfloat16 h = __float2bfloat16(v);
        float r = v - __bfloat162float(h);
        bhi[(size_t)n * DD + k] = h;
        blo[(size_t)n * DD + k] = __float2bfloat16(r);
    }
}

// ======================= middle kernels =====================================
__global__ __launch_bounds__(256) void logits_kernel(
    const float* __restrict__ X, const float* __restrict__ W,
    const float* __restrict__ mask, float* __restrict__ logits)
{
    const int m = blockIdx.x;
    const int b = m >> 11;
    const int s = m & (SS - 1);
    const int tid = threadIdx.x;
    const int h = tid >> 4, g = tid & 15;
    const float* xrow = X + (size_t)m * DD;

    float acc = 0.f;
    #pragma unroll 4
    for (int d = g; d < DD; d += 16)
        acc += xrow[d] * W[d * HH + h];

    __shared__ float red[256];
    red[tid] = acc;
    __syncthreads();
    if (tid < HH) {
        float v = 0.f;
        #pragma unroll
        for (int g2 = 0; g2 < 16; g2++) v += red[tid * 16 + g2];
        logits[((size_t)(b * HH + tid)) * SS + s] =
            v * 0.125f - (1.f - mask[m]) * 1e8f;
    }
}

__global__ __launch_bounds__(256) void softmax_wsum_kernel(
    const float* __restrict__ logits, const float* __restrict__ src,
    float* __restrict__ gout, long strideB, long strideH, int strideS)
{
    const int b = blockIdx.x >> 4, h = blockIdx.x & 15;
    const int tid = threadIdx.x;
    const float* lrow = logits + (size_t)(b * HH + h) * SS;

    __shared__ float att[SS];
    __shared__ float red[256];

    float mx = -3.4e38f;
    for (int s = tid; s < SS; s += 256) mx = fmaxf(mx, lrow[s]);
    red[tid] = mx; __syncthreads();
    for (int off = 128; off > 0; off >>= 1) {
        if (tid < off) red[tid] = fmaxf(red[tid], red[tid + off]);
        __syncthreads();
    }
    mx = red[0];
    __syncthreads();

    float sum = 0.f;
    for (int s = tid; s < SS; s += 256) {
        float e = expf(lrow[s] - mx);
        att[s] = e;
        sum += e;
    }
    red[tid] = sum; __syncthreads();
    for (int off = 128; off > 0; off >>= 1) {
        if (tid < off) red[tid] += red[tid + off];
        __syncthreads();
    }
    const float inv = 1.f / red[0];
    __syncthreads();

    const int dh = tid & 63, j = tid >> 6;
    const float* base = src + (size_t)b * strideB + (size_t)h * strideH + dh;
    float acc = 0.f;
    for (int s = j; s < SS; s += 4)
        acc += att[s] * base[(size_t)s * strideS];

    red[tid] = acc; __syncthreads();
    if (j == 0) {
        acc = red[dh] + red[64 + dh] + red[128 + dh] + red[192 + dh];
        gout[(b * HH + h) * DHH + dh] = acc * inv;
    }
}

__global__ __launch_bounds__(256) void scale_qk_kernel()
{
    const int idx = blockIdx.x * 256 + threadIdx.x;
    const int b  = idx >> 21;
    const int h  = (idx >> 17) & 15;
    const int s  = (idx >> 6) & 2047;
    const int dh = idx & 63;
    g_QK[idx] = g_K[((size_t)(b * SS + s)) * DD + h * DHH + dh]
              * g_gq[(b * HH + h) * DHH + dh];
}

// ===========================================================================
extern "C" void kernel_launch(void* const* d_in, const int* in_sizes, int n_in,
                              void* d_out, int out_size)
{
    const float* Qseq  = (const float*)d_in[0];
    const float* Kseq  = (const float*)d_in[1];
    const float* Qmask = (const float*)d_in[2];
    const float* Kmask = (const float*)d_in[3];
    const float* WQ    = (const float*)d_in[4];
    const float* WK    = (const float*)d_in[5];
    const float* Wq    = (const float*)d_in[6];
    const float* Wk    = (const float*)d_in[7];
    const float* WP    = (const float*)d_in[8];
    float* out = (float*)d_out;

    float *pQ, *pK, *pQK, *pL, *pgq, *pgk;
    __nv_bfloat16 *pBhi, *pBlo;
    cudaGetSymbolAddress((void**)&pQ,   g_Q);
    cudaGetSymbolAddress((void**)&pK,   g_K);
    cudaGetSymbolAddress((void**)&pQK,  g_QK);
    cudaGetSymbolAddress((void**)&pL,   g_logits);
    cudaGetSymbolAddress((void**)&pgq,  g_gq);
    cudaGetSymbolAddress((void**)&pgk,  g_gk);
    cudaGetSymbolAddress((void**)&pBhi, g_Bhi);
    cudaGetSymbolAddress((void**)&pBlo, g_Blo);

    cudaFuncSetAttribute(hmma_gemm_kernel<false, false>,
                         cudaFuncAttributeMaxDynamicSharedMemorySize, GEMM_SMEM);
    cudaFuncSetAttribute(hmma_gemm_kernel<true, true>,
                         cudaFuncAttributeMaxDynamicSharedMemorySize, GEMM_SMEM);

    const dim3 gg(DD / 64, MM / 128);    // (16, 128)
    const dim3 wg(DD / 32, DD / 32);     // (32, 32)

    // 1) Q = Q_seq @ WQ
    wsplit_kernel<<<wg, 256>>>(WQ, pBhi, pBlo);
    hmma_gemm_kernel<false, false><<<gg, 256, GEMM_SMEM>>>(
        Qseq, pBhi, pBlo, pQ, nullptr, nullptr);

    // 2) K = K_seq @ WK
    wsplit_kernel<<<wg, 256>>>(WK, pBhi, pBlo);
    hmma_gemm_kernel<false, false><<<gg, 256, GEMM_SMEM>>>(
        Kseq, pBhi, pBlo, pK, nullptr, nullptr);

    // 3) q logits + softmax + global_q
    logits_kernel<<<MM, 256>>>(pQ, Wq, Qmask, pL);
    softmax_wsum_kernel<<<BB * HH, 256>>>(pL, pQ, pgq,
                                          (long)SS * DD, (long)DHH, DD);

    // 4) QK = Kh * global_q  (stored (B,H,S,DH) contiguous)
    scale_qk_kernel<<<(BB * SS * DD) / 256, 256>>>();

    // 5) k logits + softmax + global_k
    logits_kernel<<<MM, 256>>>(pQK, Wk, Kmask, pL);
    softmax_wsum_kernel<<<BB * HH, 256>>>(pL, pQK, pgk,
                                          (long)HH * SS * DHH, (long)SS * DHH, DHH);

    // 6) out = ((gk ⊙ Q) @ WP) + Q
    wsplit_kernel<<<wg, 256>>>(WP, pBhi, pBlo);
    hmma_gemm_kernel<true, true><<<gg, 256, GEMM_SMEM>>>(
        pQ, pBhi, pBlo, out, pgk, pQ);
}